// round 15
// baseline (speedup 1.0000x reference)
#include <cuda_runtime.h>
#include <cuda_fp16.h>

// Problem constants (fixed by the dataset)
#define BB    2
#define NEV   262144          // 2^18 events per batch
#define DBASE 10
#define HH    256
#define WW    256
#define RR    11              // base + 1 references
#define NCH   (BB * 2 * RR)   // 44 channels = (b, pol, r)

// 2x2-pixel tiled fp16 accumulator.
// Cell = uint4 = 4 x (f16x2) = pixels (dy,dx) in order w[dy*2+dx] = {iwe, iwt}.
// 4 parity grids g = (y0&1)*2 + (x0&1): window origin (x0, y0) maps to ONE cell.
// Tile index tx = x0>>1 (arith shift; x0=-1 -> -1), plane padded by +1 each side.
#define TW    129             // tiles per row incl. pad (tx+1 in [0,128])
#define TPL   (TW * TW)       // 16641 cells per channel plane
#define GRIDSZ ((size_t)NCH * TPL)
#define TOTCELLS (4 * GRIDSZ) // ~2.93M cells * 16 B = ~47 MB

__device__ __align__(16) uint4 g_h[TOTCELLS];
__device__ float g_small[BB * RR * 2 + 2];   // partials {loss, inside} x22 + counter
                                             // zero-init; reduce kernel self-resets

// one warp per (pair, tile-row, half-row): 22 * 128 * 2 = 5632 warps
#define NWARP  (22 * 128 * 2)
#define NRBLK  (NWARP / 8)                    // 704 blocks of 8 warps

#define FULLM 0xFFFFFFFFu

// ---------------------------------------------------------------------------
// Kernel 1: per-event flow sample + bilinear scatter (ONE v4.f16x2 RED per ref)
// ---------------------------------------------------------------------------
__global__ void __launch_bounds__(256)
cm_scatter_kernel(const float* __restrict__ events,
                  const float2* __restrict__ flow) {
    // stage 256 event records (1280 floats) coalesced through SMEM
    __shared__ float sev[5 * 256];
    {
        const float* src = events + (size_t)blockIdx.x * (256 * 5);
        #pragma unroll
        for (int k = 0; k < 5; k++)
            sev[k * 256 + threadIdx.x] = src[k * 256 + threadIdx.x];
        __syncthreads();
    }
    int e = blockIdx.x * 256 + threadIdx.x;    // grid is exact: 2048*256 = BB*NEV
    int b = e >> 18;                            // e / NEV

    const float* ev = sev + threadIdx.x * 5;   // stride 5 -> conflict-free LDS
    float x  = ev[0];
    float y  = ev[1];
    float t  = ev[2];
    float ts = ev[3];
    float p  = ev[4];

    int pi = min(max((int)p, 0), 1);
    int zi = min(max((int)floorf(t), 0), DBASE - 1);

    // --- bilinear flow sample at (x, y), border-clamped like reference ---
    int sx0 = min(max((int)floorf(x), 0), WW - 2);
    int sy0 = min(max((int)floorf(y), 0), HH - 2);
    float fx = fminf(fmaxf(x - (float)sx0, 0.f), 1.f);
    float fy = fminf(fmaxf(y - (float)sy0, 0.f), 1.f);

    const float2* fm = flow + (((size_t)(b * DBASE + zi) * HH + sy0) * WW + sx0);
    float2 f00 = fm[0];
    float2 f01 = fm[1];
    float2 f10 = fm[WW];
    float2 f11 = fm[WW + 1];

    float w00s = (1.f - fx) * (1.f - fy);
    float w01s = fx * (1.f - fy);
    float w10s = (1.f - fx) * fy;
    float w11s = fx * fy;
    float fu = w00s * f00.x + w01s * f01.x + w10s * f10.x + w11s * f11.x;
    float fv = w00s * f00.y + w01s * f01.y + w10s * f10.y + w11s * f11.y;

    const size_t chbase = (size_t)((b * 2 + pi) * RR) * TPL;

    #pragma unroll
    for (int r = 0; r < RR; r++) {
        float dt = (float)r - t;
        float wx = fmaf(dt, fu, x);
        float wy = fmaf(dt, fv, y);
        float flx = floorf(wx);
        float fly = floorf(wy);
        int x0 = (int)flx;
        int y0 = (int)fly;

        // window origin must lie in [-1, 255] on both axes to touch any pixel
        if ((unsigned)(x0 + 1) > 256u) continue;
        if ((unsigned)(y0 + 1) > 256u) continue;

        float ax = wx - flx;
        float ay = wy - fly;
        float wl = (x0 == -1)     ? 0.f : 1.f - ax;   // left column
        float wr = (x0 == WW - 1) ? 0.f : ax;         // right column
        float st = (y0 == -1)     ? 0.f : 1.f - ay;   // top row
        float sb = (y0 == HH - 1) ? 0.f : ay;         // bottom row

        float c00 = wl * st, c01 = wr * st;
        float c10 = wl * sb, c11 = wr * sb;

        __half2 h0 = __floats2half2_rn(c00, c00 * ts);
        __half2 h1 = __floats2half2_rn(c01, c01 * ts);
        __half2 h2 = __floats2half2_rn(c10, c10 * ts);
        __half2 h3 = __floats2half2_rn(c11, c11 * ts);
        unsigned u0 = *reinterpret_cast<unsigned*>(&h0);
        unsigned u1 = *reinterpret_cast<unsigned*>(&h1);
        unsigned u2 = *reinterpret_cast<unsigned*>(&h2);
        unsigned u3 = *reinterpret_cast<unsigned*>(&h3);

        int g = ((y0 & 1) << 1) | (x0 & 1);
        uint4* cell = g_h + (size_t)g * GRIDSZ + chbase + (size_t)r * TPL
                    + (size_t)((y0 >> 1) + 1) * TW + ((x0 >> 1) + 1);

        asm volatile("red.global.add.noftz.v4.f16x2 [%0], {%1, %2, %3, %4};"
                     :: "l"(cell), "r"(u0), "r"(u1), "r"(u2), "r"(u3)
                     : "memory");
    }
}

// ---------------------------------------------------------------------------
// Kernel 2: warp-per-half-row gather-reduce + fused finalize + reset
// ---------------------------------------------------------------------------
__device__ __forceinline__ const uint4* cellp(int g, int ch, int ty, int tx) {
    return g_h + (size_t)g * GRIDSZ + (size_t)ch * TPL + (size_t)(ty + 1) * TW + (tx + 1);
}

__device__ __forceinline__ unsigned left_of(unsigned v, unsigned carry, int lane) {
    unsigned t = __shfl_up_sync(FULLM, v, 1);
    return (lane == 0) ? carry : t;
}

// sum four f16x2 words -> float2 {iwe, iwt}
__device__ __forceinline__ float2 sum4h(unsigned a, unsigned b, unsigned c, unsigned d) {
    __half2 s = __hadd2(__hadd2(*reinterpret_cast<__half2*>(&a),
                                *reinterpret_cast<__half2*>(&b)),
                        __hadd2(*reinterpret_cast<__half2*>(&c),
                                *reinterpret_cast<__half2*>(&d)));
    return __half22float2(s);
}

__global__ void __launch_bounds__(256)
cm_reduce_kernel(float* __restrict__ out) {
    const int gwarp = (blockIdx.x * blockDim.x + threadIdx.x) >> 5;  // 0..5631
    const int lane = threadIdx.x & 31;
    const int pair = gwarp >> 8;                 // 0..21  (= br index)
    const int rem  = gwarp & 255;
    const int j    = rem >> 1;                   // tile row 0..127
    const int half = rem & 1;                    // half-row: tiles [half*64, half*64+63]
    const int tbase = half * 64;
    const int b = pair / RR;
    const int r = pair - b * RR;
    const int chN = (b * 2 + 0) * RR + r;
    const int chP = (b * 2 + 1) * RR + r;

    float loss = 0.f;
    float inside = 0.f;

    // carries = left-neighbor scalars for lane 0; init from tile tbase-1
    // (half=0: pad column, guaranteed zero; half=1: real cells at tile 63)
    unsigned cBny, cBnw, cD0nw, cD1ny, cBpy, cBpw, cD0pw, cD1py;
    {
        uint4 Bn  = __ldg(cellp(1, chN, j, tbase - 1));
        uint4 D0n = __ldg(cellp(3, chN, j - 1, tbase - 1));
        uint4 D1n = __ldg(cellp(3, chN, j, tbase - 1));
        cBny = Bn.y; cBnw = Bn.w; cD0nw = D0n.w; cD1ny = D1n.y;
        uint4 Bp  = __ldg(cellp(1, chP, j, tbase - 1));
        uint4 D0p = __ldg(cellp(3, chP, j - 1, tbase - 1));
        uint4 D1p = __ldg(cellp(3, chP, j, tbase - 1));
        cBpy = Bp.y; cBpw = Bp.w; cD0pw = D0p.w; cD1py = D1p.y;
    }

    #pragma unroll
    for (int s = 0; s < 2; s++) {
        const int i = tbase + s * 32 + lane;     // tile col

        uint4 An  = __ldg(cellp(0, chN, j, i));
        uint4 Bn  = __ldg(cellp(1, chN, j, i));
        uint4 C0n = __ldg(cellp(2, chN, j - 1, i));
        uint4 C1n = __ldg(cellp(2, chN, j, i));
        uint4 D0n = __ldg(cellp(3, chN, j - 1, i));
        uint4 D1n = __ldg(cellp(3, chN, j, i));
        uint4 Ap  = __ldg(cellp(0, chP, j, i));
        uint4 Bp  = __ldg(cellp(1, chP, j, i));
        uint4 C0p = __ldg(cellp(2, chP, j - 1, i));
        uint4 C1p = __ldg(cellp(2, chP, j, i));
        uint4 D0p = __ldg(cellp(3, chP, j - 1, i));
        uint4 D1p = __ldg(cellp(3, chP, j, i));

        // left-neighbor scalars via shfl (lane 0 uses carry)
        unsigned lBny  = left_of(Bn.y,  cBny,  lane);
        unsigned lBnw  = left_of(Bn.w,  cBnw,  lane);
        unsigned lD0nw = left_of(D0n.w, cD0nw, lane);
        unsigned lD1ny = left_of(D1n.y, cD1ny, lane);
        unsigned lBpy  = left_of(Bp.y,  cBpy,  lane);
        unsigned lBpw  = left_of(Bp.w,  cBpw,  lane);
        unsigned lD0pw = left_of(D0p.w, cD0pw, lane);
        unsigned lD1py = left_of(D1p.y, cD1py, lane);

        // carries for next step = this step's lane 31
        cBny  = __shfl_sync(FULLM, Bn.y,  31);
        cBnw  = __shfl_sync(FULLM, Bn.w,  31);
        cD0nw = __shfl_sync(FULLM, D0n.w, 31);
        cD1ny = __shfl_sync(FULLM, D1n.y, 31);
        cBpy  = __shfl_sync(FULLM, Bp.y,  31);
        cBpw  = __shfl_sync(FULLM, Bp.w,  31);
        cD0pw = __shfl_sync(FULLM, D0p.w, 31);
        cD1py = __shfl_sync(FULLM, D1p.y, 31);

        // pixel accumulators (mapping identical to validated gather version)
        float2 n00 = sum4h(An.x, lBny, C0n.z, lD0nw);
        float2 n10 = sum4h(An.y, Bn.x, C0n.w, D0n.z);
        float2 n01 = sum4h(An.z, lBnw, C1n.x, lD1ny);
        float2 n11 = sum4h(An.w, Bn.z, C1n.y, D1n.x);
        float2 q00 = sum4h(Ap.x, lBpy, C0p.z, lD0pw);
        float2 q10 = sum4h(Ap.y, Bp.x, C0p.w, D0p.z);
        float2 q01 = sum4h(Ap.z, lBpw, C1p.x, lD1py);
        float2 q11 = sum4h(Ap.w, Bp.z, C1p.y, D1p.x);

        float a;
        a = n00.y / (n00.x + 1e-9f); loss = fmaf(a, a, loss);
        a = n10.y / (n10.x + 1e-9f); loss = fmaf(a, a, loss);
        a = n01.y / (n01.x + 1e-9f); loss = fmaf(a, a, loss);
        a = n11.y / (n11.x + 1e-9f); loss = fmaf(a, a, loss);
        a = q00.y / (q00.x + 1e-9f); loss = fmaf(a, a, loss);
        a = q10.y / (q10.x + 1e-9f); loss = fmaf(a, a, loss);
        a = q01.y / (q01.x + 1e-9f); loss = fmaf(a, a, loss);
        a = q11.y / (q11.x + 1e-9f); loss = fmaf(a, a, loss);

        if (n00.x + q00.x > 0.f) inside += 1.f;
        if (n10.x + q10.x > 0.f) inside += 1.f;
        if (n01.x + q01.x > 0.f) inside += 1.f;
        if (n11.x + q11.x > 0.f) inside += 1.f;
    }

    // warp reduction
    #pragma unroll
    for (int o = 16; o > 0; o >>= 1) {
        loss   += __shfl_xor_sync(FULLM, loss, o);
        inside += __shfl_xor_sync(FULLM, inside, o);
    }

    int done = 0;
    if (lane == 0) {
        atomicAdd(&g_small[pair * 2 + 0], loss);
        atomicAdd(&g_small[pair * 2 + 1], inside);
        __threadfence();
        int* cnt = reinterpret_cast<int*>(&g_small[BB * RR * 2]);
        done = atomicAdd(cnt, 1);
    }
    done = __shfl_sync(FULLM, done, 0);

    if (done == NWARP - 1) {                     // last warp finalizes + resets
        if (lane < BB * RR) {
            float lv = atomicAdd(&g_small[lane * 2 + 0], 0.f);
            float iv = atomicAdd(&g_small[lane * 2 + 1], 0.f);
            out[lane] = lv / (iv + 1e-9f);
            g_small[lane * 2 + 0] = 0.f;
            g_small[lane * 2 + 1] = 0.f;
        }
        __syncwarp();
        if (lane == 0)
            *reinterpret_cast<int*>(&g_small[BB * RR * 2]) = 0;  // reset counter
    }
}

// ---------------------------------------------------------------------------
extern "C" void kernel_launch(void* const* d_in, const int* in_sizes, int n_in,
                              void* d_out, int out_size) {
    const float*  events = (const float*)d_in[0];
    const float2* flow   = (const float2*)d_in[1];
    float* out = (float*)d_out;

    void* hp = nullptr;
    cudaGetSymbolAddress(&hp, g_h);

    // 1) clear accumulator grids (partials/counter self-reset in reduce)
    cudaMemsetAsync(hp, 0, sizeof(uint4) * TOTCELLS);

    // 2) scatter all B*N events into all R references (one RED per event-ref)
    cm_scatter_kernel<<<(BB * NEV) / 256, 256>>>(events, flow);

    // 3) warp-per-half-row gather-reduce; last warp finalizes the 22 outputs
    cm_reduce_kernel<<<NRBLK, 256>>>(out);
}

// round 16
// speedup vs baseline: 1.6262x; 1.6262x over previous
#include <cuda_runtime.h>
#include <cuda_fp16.h>

// Problem constants (fixed by the dataset)
#define BB    2
#define NEV   262144          // 2^18 events per batch
#define DBASE 10
#define HH    256
#define WW    256
#define RR    11              // base + 1 references
#define NCH   (BB * 2 * RR)   // 44 channels = (b, pol, r)

// 2x2-pixel tiled fp16 accumulator.
// Cell = uint4 = 4 x (f16x2) = pixels (dy,dx) in order w[dy*2+dx] = {iwe, iwt}.
// 4 parity grids g = (y0&1)*2 + (x0&1): window origin (x0, y0) maps to ONE cell.
// Tile index tx = x0>>1 (arith shift; x0=-1 -> -1), plane padded by +1 each side.
#define TW    129             // tiles per row incl. pad (tx+1 in [0,128])
#define TPL   (TW * TW)       // 16641 cells per channel plane
#define GRIDSZ ((size_t)NCH * TPL)
#define TOTCELLS (4 * GRIDSZ) // ~2.93M cells * 16 B = ~47 MB

__device__ __align__(16) uint4 g_h[TOTCELLS];
// per-pair: {loss, inside} float2 partials (22) then 22 int counters
__device__ float g_small[BB * RR * 2];
__device__ int   g_cnt[BB * RR];

#define SPLIT 32
#define NRBLK (BB * RR * SPLIT)   // 704 blocks, 2 items/thread

#define FULLM 0xFFFFFFFFu

// ---------------------------------------------------------------------------
// Kernel 1: per-event flow sample + bilinear scatter (ONE v4.f16x2 RED per ref)
// ---------------------------------------------------------------------------
__global__ void __launch_bounds__(256)
cm_scatter_kernel(const float* __restrict__ events,
                  const float2* __restrict__ flow) {
    // stage 256 event records (1280 floats) coalesced through SMEM
    __shared__ float sev[5 * 256];
    {
        const float* src = events + (size_t)blockIdx.x * (256 * 5);
        #pragma unroll
        for (int k = 0; k < 5; k++)
            sev[k * 256 + threadIdx.x] = src[k * 256 + threadIdx.x];
        __syncthreads();
    }
    int e = blockIdx.x * 256 + threadIdx.x;    // grid is exact: 2048*256 = BB*NEV
    int b = e >> 18;                            // e / NEV

    const float* ev = sev + threadIdx.x * 5;   // stride 5 -> conflict-free LDS
    float x  = ev[0];
    float y  = ev[1];
    float t  = ev[2];
    float ts = ev[3];
    float p  = ev[4];

    int pi = min(max((int)p, 0), 1);
    int zi = min(max((int)floorf(t), 0), DBASE - 1);

    // --- bilinear flow sample at (x, y), border-clamped like reference ---
    int sx0 = min(max((int)floorf(x), 0), WW - 2);
    int sy0 = min(max((int)floorf(y), 0), HH - 2);
    float fx = fminf(fmaxf(x - (float)sx0, 0.f), 1.f);
    float fy = fminf(fmaxf(y - (float)sy0, 0.f), 1.f);

    const float2* fm = flow + (((size_t)(b * DBASE + zi) * HH + sy0) * WW + sx0);
    float2 f00 = fm[0];
    float2 f01 = fm[1];
    float2 f10 = fm[WW];
    float2 f11 = fm[WW + 1];

    float w00s = (1.f - fx) * (1.f - fy);
    float w01s = fx * (1.f - fy);
    float w10s = (1.f - fx) * fy;
    float w11s = fx * fy;
    float fu = w00s * f00.x + w01s * f01.x + w10s * f10.x + w11s * f11.x;
    float fv = w00s * f00.y + w01s * f01.y + w10s * f10.y + w11s * f11.y;

    const size_t chbase = (size_t)((b * 2 + pi) * RR) * TPL;

    #pragma unroll
    for (int r = 0; r < RR; r++) {
        float dt = (float)r - t;
        float wx = fmaf(dt, fu, x);
        float wy = fmaf(dt, fv, y);
        float flx = floorf(wx);
        float fly = floorf(wy);
        int x0 = (int)flx;
        int y0 = (int)fly;

        // window origin must lie in [-1, 255] on both axes to touch any pixel
        if ((unsigned)(x0 + 1) > 256u) continue;
        if ((unsigned)(y0 + 1) > 256u) continue;

        float ax = wx - flx;
        float ay = wy - fly;
        float wl = (x0 == -1)     ? 0.f : 1.f - ax;   // left column
        float wr = (x0 == WW - 1) ? 0.f : ax;         // right column
        float st = (y0 == -1)     ? 0.f : 1.f - ay;   // top row
        float sb = (y0 == HH - 1) ? 0.f : ay;         // bottom row

        float c00 = wl * st, c01 = wr * st;
        float c10 = wl * sb, c11 = wr * sb;

        __half2 h0 = __floats2half2_rn(c00, c00 * ts);
        __half2 h1 = __floats2half2_rn(c01, c01 * ts);
        __half2 h2 = __floats2half2_rn(c10, c10 * ts);
        __half2 h3 = __floats2half2_rn(c11, c11 * ts);
        unsigned u0 = *reinterpret_cast<unsigned*>(&h0);
        unsigned u1 = *reinterpret_cast<unsigned*>(&h1);
        unsigned u2 = *reinterpret_cast<unsigned*>(&h2);
        unsigned u3 = *reinterpret_cast<unsigned*>(&h3);

        int g = ((y0 & 1) << 1) | (x0 & 1);
        uint4* cell = g_h + (size_t)g * GRIDSZ + chbase + (size_t)r * TPL
                    + (size_t)((y0 >> 1) + 1) * TW + ((x0 >> 1) + 1);

        asm volatile("red.global.add.noftz.v4.f16x2 [%0], {%1, %2, %3, %4};"
                     :: "l"(cell), "r"(u0), "r"(u1), "r"(u2), "r"(u3)
                     : "memory");
    }
}

// ---------------------------------------------------------------------------
// Kernel 2: gather-reduce (2 tile-blocks per thread) + per-pair finalize
// ---------------------------------------------------------------------------
__device__ __forceinline__ const uint4* cellp(int g, int ch, int ty, int tx) {
    return g_h + (size_t)g * GRIDSZ + (size_t)ch * TPL + (size_t)(ty + 1) * TW + (tx + 1);
}

__device__ __forceinline__ void acch(float2& a, unsigned w) {
    __half2 h = *reinterpret_cast<__half2*>(&w);
    float2 f = __half22float2(h);
    a.x += f.x;
    a.y += f.y;
}

// gather the 4 pixel accumulators of aligned 2x2 block (i, j) for channel ch
__device__ __forceinline__ void gather_block(int ch, int i, int j,
                                             float2& p00, float2& p10,
                                             float2& p01, float2& p11) {
    uint4 A   = __ldg(cellp(0, ch, j,     i));
    uint4 B0  = __ldg(cellp(1, ch, j,     i - 1));
    uint4 B1  = __ldg(cellp(1, ch, j,     i));
    uint4 C0  = __ldg(cellp(2, ch, j - 1, i));
    uint4 C1  = __ldg(cellp(2, ch, j,     i));
    uint4 D00 = __ldg(cellp(3, ch, j - 1, i - 1));
    uint4 D01 = __ldg(cellp(3, ch, j - 1, i));
    uint4 D10 = __ldg(cellp(3, ch, j,     i - 1));
    uint4 D11 = __ldg(cellp(3, ch, j,     i));

    p00 = make_float2(0.f, 0.f); p10 = make_float2(0.f, 0.f);
    p01 = make_float2(0.f, 0.f); p11 = make_float2(0.f, 0.f);
    acch(p00, A.x);  acch(p00, B0.y);  acch(p00, C0.z);  acch(p00, D00.w);
    acch(p10, A.y);  acch(p10, B1.x);  acch(p10, C0.w);  acch(p10, D01.z);
    acch(p01, A.z);  acch(p01, B0.w);  acch(p01, C1.x);  acch(p01, D10.y);
    acch(p11, A.w);  acch(p11, B1.z);  acch(p11, C1.y);  acch(p11, D11.x);
}

__device__ __forceinline__ void item_accum(int chN, int chP, int item,
                                           float& loss, float& inside) {
    const int j = item >> 7;                    // tile row  0..127
    const int i = item & 127;                   // tile col  0..127

    float2 n00, n10, n01, n11;
    gather_block(chN, i, j, n00, n10, n01, n11);
    float2 q00, q10, q01, q11;
    gather_block(chP, i, j, q00, q10, q01, q11);

    float a;
    a = n00.y / (n00.x + 1e-9f); loss = fmaf(a, a, loss);
    a = n10.y / (n10.x + 1e-9f); loss = fmaf(a, a, loss);
    a = n01.y / (n01.x + 1e-9f); loss = fmaf(a, a, loss);
    a = n11.y / (n11.x + 1e-9f); loss = fmaf(a, a, loss);
    a = q00.y / (q00.x + 1e-9f); loss = fmaf(a, a, loss);
    a = q10.y / (q10.x + 1e-9f); loss = fmaf(a, a, loss);
    a = q01.y / (q01.x + 1e-9f); loss = fmaf(a, a, loss);
    a = q11.y / (q11.x + 1e-9f); loss = fmaf(a, a, loss);

    if (n00.x + q00.x > 0.f) inside += 1.f;
    if (n10.x + q10.x > 0.f) inside += 1.f;
    if (n01.x + q01.x > 0.f) inside += 1.f;
    if (n11.x + q11.x > 0.f) inside += 1.f;
}

__global__ void __launch_bounds__(256)
cm_reduce_kernel(float* __restrict__ out) {
    const int blk = blockIdx.x;
    const int br = blk / SPLIT;                 // 0 .. B*R-1  (pair index)
    const int part = blk % SPLIT;
    const int b = br / RR;
    const int r = br % RR;
    const int tid = threadIdx.x;

    const int chN = (b * 2 + 0) * RR + r;
    const int chP = (b * 2 + 1) * RR + r;

    // this block covers 512 tile-blocks; each thread takes 2 (tid, tid+256)
    const int base = part * 512;                // of 16384 per channel pair

    float loss = 0.f;
    float inside = 0.f;
    item_accum(chN, chP, base + tid,       loss, inside);
    item_accum(chN, chP, base + tid + 256, loss, inside);

    __shared__ float sl[256];
    __shared__ float si[256];
    sl[tid] = loss;
    si[tid] = inside;
    __syncthreads();
    for (int s = 128; s > 0; s >>= 1) {
        if (tid < s) {
            sl[tid] += sl[tid + s];
            si[tid] += si[tid + s];
        }
        __syncthreads();
    }

    // per-pair accumulation + per-pair completion counter (22 independent
    // counters -> max 32 serialized atomics per address instead of 704 on one)
    if (tid == 0) {
        atomicAdd(&g_small[br * 2 + 0], sl[0]);
        atomicAdd(&g_small[br * 2 + 1], si[0]);
        __threadfence();
        int done = atomicAdd(&g_cnt[br], 1);
        if (done == SPLIT - 1) {
            // last block of THIS pair finalizes it
            float lv = atomicAdd(&g_small[br * 2 + 0], 0.f);
            float iv = atomicAdd(&g_small[br * 2 + 1], 0.f);
            out[br] = lv / (iv + 1e-9f);
            // reset for next replay
            g_small[br * 2 + 0] = 0.f;
            g_small[br * 2 + 1] = 0.f;
            __threadfence();
            g_cnt[br] = 0;
        }
    }
}

// ---------------------------------------------------------------------------
extern "C" void kernel_launch(void* const* d_in, const int* in_sizes, int n_in,
                              void* d_out, int out_size) {
    const float*  events = (const float*)d_in[0];
    const float2* flow   = (const float2*)d_in[1];
    float* out = (float*)d_out;

    void* hp = nullptr;
    cudaGetSymbolAddress(&hp, g_h);

    // 1) clear accumulator grids (partials/counters self-reset in reduce)
    cudaMemsetAsync(hp, 0, sizeof(uint4) * TOTCELLS);

    // 2) scatter all B*N events into all R references (one RED per event-ref)
    cm_scatter_kernel<<<(BB * NEV) / 256, 256>>>(events, flow);

    // 3) gather-reduce; last block of each pair finalizes that output
    cm_reduce_kernel<<<NRBLK, 256>>>(out);
}